// round 12
// baseline (speedup 1.0000x reference)
#include <cuda_runtime.h>
#include <math_constants.h>

// Problem constants
#define BQ    2
#define NQ    8192
#define KNN   16
#define QPW   4                        // queries per warp
#define WPB   8                        // warps per block
#define BLOCK 256
#define QPB   (QPW * WPB)              // 32 queries per block
#define TILE  2048                     // candidates per smem tile (32 KB of float4)
#define BLOCKS_PER_BATCH (NQ / QPB)    // 256
#define NBLK  (BQ * BLOCKS_PER_BATCH)  // 512
#define FULL  0xffffffffu
#define TOTAL_EDGES ((double)(BQ) * (double)(NQ) * (double)(KNN))

// Deterministic per-block partial sums (no atomics -> same result every replay)
__device__ float g_partials[NBLK];

// Stable insert of (v, vi) into a warp-distributed sorted top-16
// (lane l < 16 holds the (l+1)-th smallest). Stale values (v >= current 16th)
// give pos==16 -> no-op for lanes < 16. Ties keep the earlier (lower-index)
// element first -> matches jax.lax.top_k stability.
__device__ __forceinline__ void insert_event(float v, int vi, int lane,
                                             float& kd, int& ki)
{
    const unsigned le  = __ballot_sync(FULL, (lane < KNN) && (kd <= v));
    const int      pos = __popc(le);
    const float kdu = __shfl_up_sync(FULL, kd, 1);
    const int   kiu = __shfl_up_sync(FULL, ki, 1);
    if (lane >= pos) {
        kd = (lane == pos) ? v  : kdu;
        ki = (lane == pos) ? vi : kiu;
    }
}

// Full ascending bitonic sort of one value per lane (verified network, R10).
__device__ __forceinline__ float bitonic_sort32(float val, int lane)
{
#pragma unroll
    for (int k = 2; k <= 32; k <<= 1) {
#pragma unroll
        for (int j = k >> 1; j >= 1; j >>= 1) {
            float o = __shfl_xor_sync(FULL, val, j);
            bool up = ((lane & k) == 0);
            bool tm = (up == ((lane & j) == 0));
            val = tm ? fminf(val, o) : fmaxf(val, o);
        }
    }
    return val;
}

__global__ __launch_bounds__(BLOCK)
void knn_loss_kernel(const float* __restrict__ points_ref,
                     const float* __restrict__ points)
{
    __shared__ float4 tile[TILE];      // (x, y, z, x^2+y^2+z^2)
    __shared__ float  wsum[WPB];

    const int tid  = threadIdx.x;
    const int wid  = tid >> 5;
    const int lane = tid & 31;
    const int b    = blockIdx.x / BLOCKS_PER_BATCH;
    const int q0   = (blockIdx.x % BLOCKS_PER_BATCH) * QPB + wid * QPW; // first of 4 queries

    const float* __restrict__ pr = points_ref + (size_t)b * NQ * 3;
    const float* __restrict__ pp = points     + (size_t)b * NQ * 3;

    // Query points (ref cloud) + squared norms (same expansion as reference).
    float qx[QPW], qy[QPW], qz[QPW], sq[QPW];
#pragma unroll
    for (int q = 0; q < QPW; ++q) {
        qx[q] = pr[(q0 + q) * 3 + 0];
        qy[q] = pr[(q0 + q) * 3 + 1];
        qz[q] = pr[(q0 + q) * 3 + 2];
        sq[q] = qx[q] * qx[q] + qy[q] * qy[q] + qz[q] * qz[q];
    }

    // Per-query warp-distributed sorted top-16
    float kd[QPW], thr[QPW];
    int   ki[QPW];
#pragma unroll
    for (int q = 0; q < QPW; ++q) { kd[q] = CUDART_INF_F; ki[q] = -1; thr[q] = CUDART_INF_F; }

    for (int t0 = 0; t0 < NQ; t0 += TILE) {
        __syncthreads();
        // Cooperative tile load: 2048 points, 8 per thread; precompute sq.
        for (int i = tid; i < TILE; i += BLOCK) {
            int   m = t0 + i;
            float x = pr[m * 3 + 0];
            float y = pr[m * 3 + 1];
            float z = pr[m * 3 + 2];
            tile[i] = make_float4(x, y, z, x * x + y * y + z * z);
        }
        __syncthreads();

        if (t0 == 0) {
            // ---- Warm start: vote-free per-lane TOP-2 min-scan of tile 0 ----
            float m1[QPW], m2[QPW];
#pragma unroll
            for (int q = 0; q < QPW; ++q) { m1[q] = CUDART_INF_F; m2[q] = CUDART_INF_F; }
            for (int s = 0; s < TILE; s += 64) {
                const float4 c0 = tile[s + lane];
                const float4 c1 = tile[s + 32 + lane];
#pragma unroll
                for (int q = 0; q < QPW; ++q) {
                    float dot0 = fmaf(qx[q], c0.x, fmaf(qy[q], c0.y, qz[q] * c0.z));
                    float dot1 = fmaf(qx[q], c1.x, fmaf(qy[q], c1.y, qz[q] * c1.z));
                    float d0 = fmaf(-2.0f, dot0, sq[q] + c0.w);
                    float d1 = fmaf(-2.0f, dot1, sq[q] + c1.w);
                    const unsigned rel = (unsigned)(q0 + q - s);
                    if (rel < 64u && lane == (int)(rel & 31u)) {
                        if (rel < 32u) d0 = CUDART_INF_F; else d1 = CUDART_INF_F;
                    }
                    // branchless top-2 update (twice)
                    float t = fminf(m1[q], d0);
                    m2[q] = fminf(m2[q], fmaxf(m1[q], d0));
                    m1[q] = t;
                    t = fminf(m1[q], d1);
                    m2[q] = fminf(m2[q], fmaxf(m1[q], d1));
                    m1[q] = t;
                }
            }
            // T = 16th smallest of the 64 values {m1, m2}: each lane contributes
            // <=2 genuine distinct non-self candidates, so the 16 smallest of the
            // union are 16 distinct candidates -> T upper-bounds true 16th-NN d2.
#pragma unroll
            for (int q = 0; q < QPW; ++q) {
                float a = bitonic_sort32(m1[q], lane);   // ascending
                float c = bitonic_sort32(m2[q], lane);   // ascending
                float cr = __shfl_xor_sync(FULL, c, 31); // reversed -> concat bitonic
                float L  = fminf(a, cr);                 // 32 smallest of the 64, bitonic
#pragma unroll
                for (int j = 16; j >= 1; j >>= 1) {      // bitonic merge cleanup (asc)
                    float o = __shfl_xor_sync(FULL, L, j);
                    L = ((lane & j) == 0) ? fminf(L, o) : fmaxf(L, o);
                }
                float T = __shfl_sync(FULL, L, KNN - 1);
                // nextafter-up so strict-< filter admits candidates with d2 == T
                thr[q] = __int_as_float(__float_as_int(T) + 1);
            }
        }

        // ---- Filtered scan: 64 candidates x 4 queries per step ----
        for (int s = 0; s < TILE; s += 64) {
            const int    sg = t0 + s;
            const float4 c0 = tile[s + lane];
            const float4 c1 = tile[s + 32 + lane];
            float d0[QPW], d1[QPW];
#pragma unroll
            for (int q = 0; q < QPW; ++q) {
                float dot0 = fmaf(qx[q], c0.x, fmaf(qy[q], c0.y, qz[q] * c0.z));
                float dot1 = fmaf(qx[q], c1.x, fmaf(qy[q], c1.y, qz[q] * c1.z));
                d0[q] = fmaf(-2.0f, dot0, sq[q] + c0.w);   // sq_n + sq_m - 2*dot
                d1[q] = fmaf(-2.0f, dot1, sq[q] + c1.w);
            }

            // Self-exclusion (rare warp-uniform branch; queries consecutive)
            if ((unsigned)(q0 + QPW - 1 - sg) < (unsigned)(64 + QPW - 1)) {
#pragma unroll
                for (int q = 0; q < QPW; ++q) {
                    const unsigned rel = (unsigned)(q0 + q - sg);
                    if (rel < 64u && lane == (int)(rel & 31u)) {
                        if (rel < 32u) d0[q] = CUDART_INF_F;
                        else           d1[q] = CUDART_INF_F;
                    }
                }
            }

            bool any = false;
#pragma unroll
            for (int q = 0; q < QPW; ++q)
                any |= (d0[q] < thr[q]) | (d1[q] < thr[q]);
            if (__ballot_sync(FULL, any)) {
#pragma unroll
                for (int q = 0; q < QPW; ++q) {
                    // Ascending candidate order within each query (stability).
                    unsigned m0 = __ballot_sync(FULL, d0[q] < thr[q]);
                    while (m0) {
                        const int   src = __ffs(m0) - 1;
                        const float v   = __shfl_sync(FULL, d0[q], src);
                        insert_event(v, sg + src, lane, kd[q], ki[q]);
                        m0 &= m0 - 1;
                    }
                    unsigned m1m = __ballot_sync(FULL, d1[q] < thr[q]);
                    while (m1m) {
                        const int   src = __ffs(m1m) - 1;
                        const float v   = __shfl_sync(FULL, d1[q], src);
                        insert_event(v, sg + 32 + src, lane, kd[q], ki[q]);
                        m1m &= m1m - 1;
                    }
                    // Refresh threshold once per hit-step (can only tighten).
                    thr[q] = fminf(thr[q], __shfl_sync(FULL, kd[q], KNN - 1));
                }
            }
        }
    }

    // ---- Edge lengths + L1: lanes 0..15 hold one neighbor per query ----
    float partial = 0.0f;
    if (lane < KNN) {
#pragma unroll
        for (int q = 0; q < QPW; ++q) {
            const int nb = ki[q];
            float rx = pr[nb * 3 + 0] - qx[q];
            float ry = pr[nb * 3 + 1] - qy[q];
            float rz = pr[nb * 3 + 2] - qz[q];
            float dref = sqrtf(rx * rx + ry * ry + rz * rz);
            float pqx = pp[(q0 + q) * 3 + 0];
            float pqy = pp[(q0 + q) * 3 + 1];
            float pqz = pp[(q0 + q) * 3 + 2];
            float px = pp[nb * 3 + 0] - pqx;
            float py = pp[nb * 3 + 1] - pqy;
            float pz = pp[nb * 3 + 2] - pqz;
            float dprd = sqrtf(px * px + py * py + pz * pz);
            partial += fabsf(dref - dprd);
        }
    }

    // Deterministic warp + block reduction
#pragma unroll
    for (int o = 16; o > 0; o >>= 1)
        partial += __shfl_xor_sync(FULL, partial, o);
    if (lane == 0) wsum[wid] = partial;
    __syncthreads();

    if (wid == 0) {
        float s = (lane < WPB) ? wsum[lane] : 0.0f;
#pragma unroll
        for (int o = 16; o > 0; o >>= 1)
            s += __shfl_xor_sync(FULL, s, o);
        if (lane == 0) g_partials[blockIdx.x] = s;
    }
}

__global__ void finalize_kernel(float* __restrict__ out)
{
    __shared__ double sred[256];
    int t = threadIdx.x;
    double s = 0.0;
    for (int i = t; i < NBLK; i += 256) s += (double)g_partials[i];
    sred[t] = s;
    __syncthreads();
#pragma unroll
    for (int st = 128; st > 0; st >>= 1) {
        if (t < st) sred[t] += sred[t + st];
        __syncthreads();
    }
    if (t == 0) out[0] = (float)(sred[0] / TOTAL_EDGES);
}

extern "C" void kernel_launch(void* const* d_in, const int* in_sizes, int n_in,
                              void* d_out, int out_size)
{
    (void)in_sizes; (void)n_in; (void)out_size;
    const float* points_ref = (const float*)d_in[0];
    const float* points     = (const float*)d_in[1];
    knn_loss_kernel<<<NBLK, BLOCK>>>(points_ref, points);
    finalize_kernel<<<1, 256>>>((float*)d_out);
}